// round 1
// baseline (speedup 1.0000x reference)
#include <cuda_runtime.h>
#include <math.h>

// ---------------- problem constants ----------------
#define B_SZ   16384
#define S_SZ   256
#define C_SZ   8
#define DIN    2048          // S*C
#define HID    512
#define LAT    64
#define NTOT   (B_SZ * DIN)  // 33,554,432

#define SOM_BLOCKS (B_SZ / 8)  // 2048 (8 samples per 256-thread block)
#define EBLK 4096              // blocks for elementwise/mse kernel

// ---------------- scratch (device globals; allocation-free rule) ----------------
__device__ float g_H1[B_SZ * HID];
__device__ float g_H2[B_SZ * HID];
__device__ float g_Z [B_SZ * LAT];
__device__ float g_Zq[B_SZ * LAT];
__device__ float g_Xq[(size_t)B_SZ * DIN];
__device__ float g_Xe[(size_t)B_SZ * DIN];

__device__ double g_commit[SOM_BLOCKS];
__device__ double g_som   [SOM_BLOCKS];
__device__ double g_mse_e [EBLK];
__device__ double g_mse_q [EBLK];

// ---------------- fused GEMM + bias + activation ----------------
// C[M,N] = act(A[M,K] @ W[K,N] + bias[N])
// ACT: 0 = relu, 1 = tanh, 2 = none
// BM=128, BN=64, BK=16, 256 threads, 8x4 register tile.
// Requires: M % 128 == 0, N % 64 == 0, K % 16 == 0 (true for all layers here).
template<int ACT>
__global__ __launch_bounds__(256) void gemm_bias_act(
    const float* __restrict__ A, const float* __restrict__ W,
    const float* __restrict__ bias, float* __restrict__ C,
    int M, int K, int N)
{
    __shared__ float As[16][132];   // [k][m], padded to reduce STS conflicts
    __shared__ float Bs[16][64];    // [k][n]

    const int tid = threadIdx.x;
    const int tx  = tid & 15;       // 0..15 -> n
    const int ty  = tid >> 4;       // 0..15 -> m
    const int m0  = blockIdx.y * 128;
    const int n0  = blockIdx.x * 64;

    float acc[8][4];
#pragma unroll
    for (int i = 0; i < 8; i++)
#pragma unroll
        for (int j = 0; j < 4; j++) acc[i][j] = 0.f;

    for (int k0 = 0; k0 < K; k0 += 16) {
        // Load A tile 128x16 (512 float4, 2 per thread), store transposed.
#pragma unroll
        for (int i = 0; i < 2; i++) {
            int f  = tid + i * 256;
            int r  = f >> 2;        // row within tile 0..127
            int c4 = f & 3;         // which float4 along k
            float4 v = *(const float4*)(A + (size_t)(m0 + r) * K + k0 + c4 * 4);
            As[c4 * 4 + 0][r] = v.x;
            As[c4 * 4 + 1][r] = v.y;
            As[c4 * 4 + 2][r] = v.z;
            As[c4 * 4 + 3][r] = v.w;
        }
        // Load B tile 16x64 (256 float4, 1 per thread).
        {
            int r  = tid >> 4;      // k row 0..15
            int c4 = tid & 15;      // float4 along n
            *(float4*)&Bs[r][c4 * 4] =
                *(const float4*)(W + (size_t)(k0 + r) * N + n0 + c4 * 4);
        }
        __syncthreads();

#pragma unroll
        for (int k = 0; k < 16; k++) {
            float a[8], b[4];
            *(float4*)&a[0] = *(const float4*)&As[k][ty * 8];
            *(float4*)&a[4] = *(const float4*)&As[k][ty * 8 + 4];
            *(float4*)&b[0] = *(const float4*)&Bs[k][tx * 4];
#pragma unroll
            for (int i = 0; i < 8; i++)
#pragma unroll
                for (int j = 0; j < 4; j++)
                    acc[i][j] = fmaf(a[i], b[j], acc[i][j]);
        }
        __syncthreads();
    }

    float bv[4];
#pragma unroll
    for (int j = 0; j < 4; j++) bv[j] = bias[n0 + tx * 4 + j];

#pragma unroll
    for (int i = 0; i < 8; i++) {
        int m = m0 + ty * 8 + i;
        float4 o;
        float* po = (float*)&o;
#pragma unroll
        for (int j = 0; j < 4; j++) {
            float v = acc[i][j] + bv[j];
            if (ACT == 0)      v = fmaxf(v, 0.f);
            else if (ACT == 1) v = tanhf(v);
            po[j] = v;
        }
        *(float4*)(C + (size_t)m * N + n0 + tx * 4) = o;
    }
}

// ---------------- SOM: argmin over 9 codes, z_q, commit & som partial losses ----
// One warp per sample; lane handles dims {lane, lane+32}. 8 samples per block.
__global__ __launch_bounds__(256) void som_kernel(
    const float* __restrict__ Z, const float* __restrict__ emb,
    float* __restrict__ Zq)
{
    const int tid  = threadIdx.x;
    const int warp = tid >> 5;
    const int lane = tid & 31;
    const int b    = blockIdx.x * 8 + warp;

    const float* z = Z + (size_t)b * LAT;
    const float z0 = z[lane];
    const float z1 = z[lane + 32];

    // squared distances to all 9 codes (full butterfly -> all lanes agree)
    float dist[9];
#pragma unroll
    for (int c = 0; c < 9; c++) {
        float e0 = emb[c * LAT + lane];
        float e1 = emb[c * LAT + lane + 32];
        float d0 = z0 - e0, d1 = z1 - e1;
        float d = d0 * d0 + d1 * d1;
#pragma unroll
        for (int o = 16; o > 0; o >>= 1)
            d += __shfl_xor_sync(0xffffffffu, d, o);
        dist[c] = d;
    }
    int k = 0;
    float dmin = dist[0];
#pragma unroll
    for (int c = 1; c < 9; c++)
        if (dist[c] < dmin) { dmin = dist[c]; k = c; }   // first-min tie break
    const int k1 = k / 3, k2 = k % 3;

    const float q0 = emb[k * LAT + lane];
    const float q1 = emb[k * LAT + lane + 32];
    Zq[(size_t)b * LAT + lane]      = q0;
    Zq[(size_t)b * LAT + lane + 32] = q1;

    float dc0 = z0 - q0, dc1 = z1 - q1;
    float commit = dc0 * dc0 + dc1 * dc1;
    float som    = commit;  // center neighbor

    // up: k1 < 2 -> (k1+1, k2); else contributes z^2 (masked to 0)
    {
        if (k1 < 2) {
            int idx = (k1 + 1) * 3 + k2;
            float e0 = emb[idx * LAT + lane], e1 = emb[idx * LAT + lane + 32];
            float a = z0 - e0, bb = z1 - e1; som += a * a + bb * bb;
        } else som += z0 * z0 + z1 * z1;
    }
    // down: k1 > 0 -> (k1-1, k2)
    {
        if (k1 > 0) {
            int idx = (k1 - 1) * 3 + k2;
            float e0 = emb[idx * LAT + lane], e1 = emb[idx * LAT + lane + 32];
            float a = z0 - e0, bb = z1 - e1; som += a * a + bb * bb;
        } else som += z0 * z0 + z1 * z1;
    }
    // right: k2 < 2 -> (k1, k2+1)
    {
        if (k2 < 2) {
            int idx = k1 * 3 + (k2 + 1);
            float e0 = emb[idx * LAT + lane], e1 = emb[idx * LAT + lane + 32];
            float a = z0 - e0, bb = z1 - e1; som += a * a + bb * bb;
        } else som += z0 * z0 + z1 * z1;
    }
    // left: k2 > 0 -> (k1, k2-1)
    {
        if (k2 > 0) {
            int idx = k1 * 3 + (k2 - 1);
            float e0 = emb[idx * LAT + lane], e1 = emb[idx * LAT + lane + 32];
            float a = z0 - e0, bb = z1 - e1; som += a * a + bb * bb;
        } else som += z0 * z0 + z1 * z1;
    }

    // deterministic block reduction into per-block partials (double)
    __shared__ double r0[256], r1[256];
    r0[tid] = (double)commit;
    r1[tid] = (double)som;
    __syncthreads();
    for (int o = 128; o > 0; o >>= 1) {
        if (tid < o) { r0[tid] += r0[tid + o]; r1[tid] += r1[tid + o]; }
        __syncthreads();
    }
    if (tid == 0) {
        g_commit[blockIdx.x] = r0[0];
        g_som[blockIdx.x]    = r1[0];
    }
}

// ---------------- elementwise: out = x_q + x_e, MSE partial sums --------------
__global__ __launch_bounds__(256) void final_elem(
    const float* __restrict__ x, float* __restrict__ out)
{
    const int tid = threadIdx.x;
    float se = 0.f, sq = 0.f;
    for (size_t i = (size_t)blockIdx.x * 256 + tid; i < (size_t)NTOT;
         i += (size_t)256 * EBLK) {
        float xv = x[i];
        float xe = g_Xe[i];
        float xq = g_Xq[i];
        out[i] = xq + xe;
        float de = xv - xe, dq = xv - xq;
        se = fmaf(de, de, se);
        sq = fmaf(dq, dq, sq);
    }
    __shared__ double r0[256], r1[256];
    r0[tid] = (double)se;
    r1[tid] = (double)sq;
    __syncthreads();
    for (int o = 128; o > 0; o >>= 1) {
        if (tid < o) { r0[tid] += r0[tid + o]; r1[tid] += r1[tid + o]; }
        __syncthreads();
    }
    if (tid == 0) {
        g_mse_e[blockIdx.x] = r0[0];
        g_mse_q[blockIdx.x] = r1[0];
    }
}

// ---------------- final loss scalar ----------------
__global__ __launch_bounds__(256) void loss_kernel(float* __restrict__ out)
{
    const int tid = threadIdx.x;
    double c = 0, s = 0, e = 0, q = 0;
    for (int i = tid; i < SOM_BLOCKS; i += 256) { c += g_commit[i]; s += g_som[i]; }
    for (int i = tid; i < EBLK; i += 256)       { e += g_mse_e[i];  q += g_mse_q[i]; }
    __shared__ double r0[256], r1[256], r2[256], r3[256];
    r0[tid] = c; r1[tid] = s; r2[tid] = e; r3[tid] = q;
    __syncthreads();
    for (int o = 128; o > 0; o >>= 1) {
        if (tid < o) {
            r0[tid] += r0[tid + o]; r1[tid] += r1[tid + o];
            r2[tid] += r2[tid + o]; r3[tid] += r3[tid + o];
        }
        __syncthreads();
    }
    if (tid == 0) {
        double mse    = (r2[0] + r3[0]) / (double)NTOT;
        double commit = r0[0] / (double)(B_SZ * LAT);
        double som    = r1[0] / (double)(B_SZ * 5 * LAT);
        out[0] = (float)(mse + commit + som);
    }
}

// ---------------- launch ----------------
extern "C" void kernel_launch(void* const* d_in, const int* in_sizes, int n_in,
                              void* d_out, int out_size)
{
    static float *pH1 = nullptr, *pH2, *pZ, *pZq, *pXq, *pXe;
    if (!pH1) {
        cudaGetSymbolAddress((void**)&pH1, g_H1);
        cudaGetSymbolAddress((void**)&pH2, g_H2);
        cudaGetSymbolAddress((void**)&pZ,  g_Z);
        cudaGetSymbolAddress((void**)&pZq, g_Zq);
        cudaGetSymbolAddress((void**)&pXq, g_Xq);
        cudaGetSymbolAddress((void**)&pXe, g_Xe);
    }

    const float* x      = (const float*)d_in[0];
    // d_in[1] = y (unused by the reference math)
    const float* enc_w1 = (const float*)d_in[2];
    const float* enc_b1 = (const float*)d_in[3];
    const float* enc_w2 = (const float*)d_in[4];
    const float* enc_b2 = (const float*)d_in[5];
    const float* enc_w3 = (const float*)d_in[6];
    const float* enc_b3 = (const float*)d_in[7];
    const float* dq_w1  = (const float*)d_in[8];
    const float* dq_b1  = (const float*)d_in[9];
    const float* dq_w2  = (const float*)d_in[10];
    const float* dq_b2  = (const float*)d_in[11];
    const float* dq_w3  = (const float*)d_in[12];
    const float* dq_b3  = (const float*)d_in[13];
    const float* de_w1  = (const float*)d_in[14];
    const float* de_b1  = (const float*)d_in[15];
    const float* de_w2  = (const float*)d_in[16];
    const float* de_b2  = (const float*)d_in[17];
    const float* de_w3  = (const float*)d_in[18];
    const float* de_b3  = (const float*)d_in[19];
    const float* emb    = (const float*)d_in[20];

    float* out = (float*)d_out;          // out[0] = loss, out[1..] = x_q + x_e

    const dim3 thr(256);
    const dim3 gHID(HID / 64, B_SZ / 128);   // N=512
    const dim3 gLAT(LAT / 64, B_SZ / 128);   // N=64
    const dim3 gDIN(DIN / 64, B_SZ / 128);   // N=2048

    // ---- encoder (fp32 exactly: protects argmin) ----
    gemm_bias_act<0><<<gHID, thr>>>(x,   enc_w1, enc_b1, pH1, B_SZ, DIN, HID);
    gemm_bias_act<0><<<gHID, thr>>>(pH1, enc_w2, enc_b2, pH2, B_SZ, HID, HID);
    gemm_bias_act<1><<<gLAT, thr>>>(pH2, enc_w3, enc_b3, pZ,  B_SZ, HID, LAT);

    // ---- SOM quantization + commit/som loss partials ----
    som_kernel<<<SOM_BLOCKS, thr>>>(pZ, emb, pZq);

    // ---- decoder on z_q ----
    gemm_bias_act<0><<<gHID, thr>>>(pZq, dq_w1, dq_b1, pH1, B_SZ, LAT, HID);
    gemm_bias_act<0><<<gHID, thr>>>(pH1, dq_w2, dq_b2, pH2, B_SZ, HID, HID);
    gemm_bias_act<2><<<gDIN, thr>>>(pH2, dq_w3, dq_b3, pXq, B_SZ, HID, DIN);

    // ---- decoder on z_e ----
    gemm_bias_act<0><<<gHID, thr>>>(pZ,  de_w1, de_b1, pH1, B_SZ, LAT, HID);
    gemm_bias_act<0><<<gHID, thr>>>(pH1, de_w2, de_b2, pH2, B_SZ, HID, HID);
    gemm_bias_act<2><<<gDIN, thr>>>(pH2, de_w3, de_b3, pXe, B_SZ, HID, DIN);

    // ---- output tensor + loss ----
    final_elem<<<EBLK, thr>>>(x, out + 1);
    loss_kernel<<<1, thr>>>(out);
}

// round 7
// speedup vs baseline: 1.7343x; 1.7343x over previous
#include <cuda_runtime.h>
#include <math.h>
#include <stdint.h>

// ---------------- problem constants ----------------
#define B_SZ   16384
#define DIN    2048          // S*C
#define HID    512
#define LAT    64
#define NTOT   (B_SZ * DIN)  // 33,554,432

#define SOM_BLOCKS (B_SZ / 8)  // 2048
#define EBLK 4096              // blocks for elementwise/mse kernel

// ---------------- scratch (device globals; allocation-free rule) --------------
__device__ float g_H1[B_SZ * HID];
__device__ float g_H2[B_SZ * HID];
__device__ float g_Z [B_SZ * LAT];
__device__ float g_Xe[(size_t)B_SZ * DIN];
__device__ int   g_K [B_SZ];

__device__ float g_T1[9 * HID];
__device__ float g_T2[9 * HID];
__device__ float g_Tq[9 * DIN];

__device__ double g_commit[SOM_BLOCKS];
__device__ double g_som   [SOM_BLOCKS];
__device__ double g_mse_e [EBLK];
__device__ double g_mse_q [EBLK];

// ---------------- fp32 GEMM + bias + activation (small encoder layer 3) -------
// ACT: 0 = relu, 1 = tanh, 2 = none
template<int ACT>
__global__ __launch_bounds__(256) void gemm_bias_act(
    const float* __restrict__ A, const float* __restrict__ W,
    const float* __restrict__ bias, float* __restrict__ C,
    int M, int K, int N)
{
    __shared__ float As[16][132];
    __shared__ float Bs[16][64];

    const int tid = threadIdx.x;
    const int tx  = tid & 15;
    const int ty  = tid >> 4;
    const int m0  = blockIdx.y * 128;
    const int n0  = blockIdx.x * 64;

    float acc[8][4];
#pragma unroll
    for (int i = 0; i < 8; i++)
#pragma unroll
        for (int j = 0; j < 4; j++) acc[i][j] = 0.f;

    for (int k0 = 0; k0 < K; k0 += 16) {
#pragma unroll
        for (int i = 0; i < 2; i++) {
            int f  = tid + i * 256;
            int r  = f >> 2;
            int c4 = f & 3;
            float4 v = *(const float4*)(A + (size_t)(m0 + r) * K + k0 + c4 * 4);
            As[c4 * 4 + 0][r] = v.x;
            As[c4 * 4 + 1][r] = v.y;
            As[c4 * 4 + 2][r] = v.z;
            As[c4 * 4 + 3][r] = v.w;
        }
        {
            int r  = tid >> 4;
            int c4 = tid & 15;
            *(float4*)&Bs[r][c4 * 4] =
                *(const float4*)(W + (size_t)(k0 + r) * N + n0 + c4 * 4);
        }
        __syncthreads();

#pragma unroll
        for (int k = 0; k < 16; k++) {
            float a[8], b[4];
            *(float4*)&a[0] = *(const float4*)&As[k][ty * 8];
            *(float4*)&a[4] = *(const float4*)&As[k][ty * 8 + 4];
            *(float4*)&b[0] = *(const float4*)&Bs[k][tx * 4];
#pragma unroll
            for (int i = 0; i < 8; i++)
#pragma unroll
                for (int j = 0; j < 4; j++)
                    acc[i][j] = fmaf(a[i], b[j], acc[i][j]);
        }
        __syncthreads();
    }

    float bv[4];
#pragma unroll
    for (int j = 0; j < 4; j++) bv[j] = bias[n0 + tx * 4 + j];

#pragma unroll
    for (int i = 0; i < 8; i++) {
        int m = m0 + ty * 8 + i;
        float4 o;
        float* po = (float*)&o;
#pragma unroll
        for (int j = 0; j < 4; j++) {
            float v = acc[i][j] + bv[j];
            if (ACT == 0)      v = fmaxf(v, 0.f);
            else if (ACT == 1) v = tanhf(v);
            po[j] = v;
        }
        *(float4*)(C + (size_t)m * N + n0 + tx * 4) = o;
    }
}

// ---------------- TF32 tensor-core GEMM (optionally error-compensated) --------
// cvt.rna.tf32.f32 requires a .b32 destination register.
__device__ __forceinline__ float to_tf32(float x) {
    uint32_t y;
    asm("cvt.rna.tf32.f32 %0, %1;" : "=r"(y) : "f"(x));
    return __uint_as_float(y);
}

__device__ __forceinline__ void mma_tf32(float* c, const uint32_t* a, const uint32_t* b) {
    asm volatile(
        "mma.sync.aligned.m16n8k8.row.col.f32.tf32.tf32.f32 "
        "{%0,%1,%2,%3}, {%4,%5,%6,%7}, {%8,%9}, {%0,%1,%2,%3};\n"
        : "+f"(c[0]), "+f"(c[1]), "+f"(c[2]), "+f"(c[3])
        : "r"(a[0]), "r"(a[1]), "r"(a[2]), "r"(a[3]), "r"(b[0]), "r"(b[1]));
}

// BM=128, BN=128, BK=16, 256 threads (8 warps, 4x2), warp tile 32x64.
// ACT: 0 = relu, 1 = tanh, 2 = none.
// SPLIT=1: 3xTF32 error-compensated (hi*hi + hi*lo + lo*hi) -> ~fp32 accuracy.
template<int ACT, int SPLIT>
__global__ __launch_bounds__(256) void gemm_tf32(
    const float* __restrict__ A, const float* __restrict__ W,
    const float* __restrict__ bias, float* __restrict__ C,
    int M, int K, int N)
{
    __shared__ float As [16][132];               // [k][m] hi
    __shared__ float Bs [16][136];               // [k][n] hi
    __shared__ float Asl[SPLIT ? 16 : 1][132];   // lo
    __shared__ float Bsl[SPLIT ? 16 : 1][136];

    const int tid  = threadIdx.x;
    const int warp = tid >> 5, lane = tid & 31;
    const int gid  = lane >> 2, t4 = lane & 3;
    const int wm   = warp >> 1, wn = warp & 1;
    const int m0   = blockIdx.y * 128, n0 = blockIdx.x * 128;

    float acc[2][8][4];
#pragma unroll
    for (int mt = 0; mt < 2; mt++)
#pragma unroll
        for (int nt = 0; nt < 8; nt++)
#pragma unroll
            for (int j = 0; j < 4; j++) acc[mt][nt][j] = 0.f;

    for (int k0 = 0; k0 < K; k0 += 16) {
        // A tile 128x16 -> As[k][m]
#pragma unroll
        for (int i = 0; i < 2; i++) {
            int f  = tid + i * 256;
            int r  = f >> 2, c4 = f & 3;
            float4 v = *(const float4*)(A + (size_t)(m0 + r) * K + k0 + c4 * 4);
            float h0 = to_tf32(v.x), h1 = to_tf32(v.y);
            float h2 = to_tf32(v.z), h3 = to_tf32(v.w);
            As[c4 * 4 + 0][r] = h0;
            As[c4 * 4 + 1][r] = h1;
            As[c4 * 4 + 2][r] = h2;
            As[c4 * 4 + 3][r] = h3;
            if (SPLIT) {
                Asl[c4 * 4 + 0][r] = to_tf32(v.x - h0);
                Asl[c4 * 4 + 1][r] = to_tf32(v.y - h1);
                Asl[c4 * 4 + 2][r] = to_tf32(v.z - h2);
                Asl[c4 * 4 + 3][r] = to_tf32(v.w - h3);
            }
        }
        // B tile 16x128 -> Bs[k][n]
#pragma unroll
        for (int i = 0; i < 2; i++) {
            int f  = tid + i * 256;
            int r  = f >> 5, c4 = f & 31;
            float4 v = *(const float4*)(W + (size_t)(k0 + r) * N + n0 + c4 * 4);
            float h0 = to_tf32(v.x), h1 = to_tf32(v.y);
            float h2 = to_tf32(v.z), h3 = to_tf32(v.w);
            Bs[r][c4 * 4 + 0] = h0;
            Bs[r][c4 * 4 + 1] = h1;
            Bs[r][c4 * 4 + 2] = h2;
            Bs[r][c4 * 4 + 3] = h3;
            if (SPLIT) {
                Bsl[r][c4 * 4 + 0] = to_tf32(v.x - h0);
                Bsl[r][c4 * 4 + 1] = to_tf32(v.y - h1);
                Bsl[r][c4 * 4 + 2] = to_tf32(v.z - h2);
                Bsl[r][c4 * 4 + 3] = to_tf32(v.w - h3);
            }
        }
        __syncthreads();

#pragma unroll
        for (int kk = 0; kk < 2; kk++) {
            const int kb = kk * 8;
            uint32_t af[2][4], afl[2][4];
#pragma unroll
            for (int mt = 0; mt < 2; mt++) {
                int rb = wm * 32 + mt * 16;
                af[mt][0] = __float_as_uint(As[kb + t4    ][rb + gid    ]);
                af[mt][1] = __float_as_uint(As[kb + t4    ][rb + gid + 8]);
                af[mt][2] = __float_as_uint(As[kb + t4 + 4][rb + gid    ]);
                af[mt][3] = __float_as_uint(As[kb + t4 + 4][rb + gid + 8]);
                if (SPLIT) {
                    afl[mt][0] = __float_as_uint(Asl[kb + t4    ][rb + gid    ]);
                    afl[mt][1] = __float_as_uint(Asl[kb + t4    ][rb + gid + 8]);
                    afl[mt][2] = __float_as_uint(Asl[kb + t4 + 4][rb + gid    ]);
                    afl[mt][3] = __float_as_uint(Asl[kb + t4 + 4][rb + gid + 8]);
                }
            }
#pragma unroll
            for (int nt = 0; nt < 8; nt++) {
                int cb = wn * 64 + nt * 8 + gid;
                uint32_t bh[2];
                bh[0] = __float_as_uint(Bs[kb + t4    ][cb]);
                bh[1] = __float_as_uint(Bs[kb + t4 + 4][cb]);
#pragma unroll
                for (int mt = 0; mt < 2; mt++)
                    mma_tf32(acc[mt][nt], af[mt], bh);
                if (SPLIT) {
                    uint32_t bl[2];
                    bl[0] = __float_as_uint(Bsl[kb + t4    ][cb]);
                    bl[1] = __float_as_uint(Bsl[kb + t4 + 4][cb]);
#pragma unroll
                    for (int mt = 0; mt < 2; mt++) {
                        mma_tf32(acc[mt][nt], af[mt], bl);   // hi_a * lo_b
                        mma_tf32(acc[mt][nt], afl[mt], bh);  // lo_a * hi_b
                    }
                }
            }
        }
        __syncthreads();
    }

    // epilogue: bias + activation, float2 stores
#pragma unroll
    for (int mt = 0; mt < 2; mt++) {
        int r0 = m0 + wm * 32 + mt * 16 + gid;
#pragma unroll
        for (int nt = 0; nt < 8; nt++) {
            int c = n0 + wn * 64 + nt * 8 + 2 * t4;
            float b0 = bias[c], b1 = bias[c + 1];
            float v00 = acc[mt][nt][0] + b0, v01 = acc[mt][nt][1] + b1;
            float v10 = acc[mt][nt][2] + b0, v11 = acc[mt][nt][3] + b1;
            if (ACT == 0) {
                v00 = fmaxf(v00, 0.f); v01 = fmaxf(v01, 0.f);
                v10 = fmaxf(v10, 0.f); v11 = fmaxf(v11, 0.f);
            } else if (ACT == 1) {
                v00 = tanhf(v00); v01 = tanhf(v01);
                v10 = tanhf(v10); v11 = tanhf(v11);
            }
            float2 lo = make_float2(v00, v01);
            float2 hi = make_float2(v10, v11);
            *(float2*)(C + (size_t)r0 * N + c)       = lo;
            *(float2*)(C + (size_t)(r0 + 8) * N + c) = hi;
        }
    }
}

// ---------------- tiny GEMM for the 9-row dq-decoder table --------------------
template<int ACT>
__global__ __launch_bounds__(256) void dq_small(
    const float* __restrict__ A, const float* __restrict__ W,
    const float* __restrict__ bias, float* __restrict__ C,
    int K, int N)
{
    const int row = blockIdx.y;
    const int n   = blockIdx.x * 256 + threadIdx.x;
    const float* a = A + (size_t)row * K;
    float acc = 0.f;
    for (int k = 0; k < K; k++)
        acc = fmaf(a[k], W[(size_t)k * N + n], acc);
    acc += bias[n];
    if (ACT == 0) acc = fmaxf(acc, 0.f);
    C[(size_t)row * N + n] = acc;
}

// ---------------- SOM: argmin over 9 codes, commit & som partial losses -------
__global__ __launch_bounds__(256) void som_kernel(
    const float* __restrict__ Z, const float* __restrict__ emb)
{
    const int tid  = threadIdx.x;
    const int warp = tid >> 5;
    const int lane = tid & 31;
    const int b    = blockIdx.x * 8 + warp;

    const float* z = Z + (size_t)b * LAT;
    const float z0 = z[lane];
    const float z1 = z[lane + 32];

    float dist[9];
#pragma unroll
    for (int c = 0; c < 9; c++) {
        float e0 = emb[c * LAT + lane];
        float e1 = emb[c * LAT + lane + 32];
        float d0 = z0 - e0, d1 = z1 - e1;
        float d = d0 * d0 + d1 * d1;
#pragma unroll
        for (int o = 16; o > 0; o >>= 1)
            d += __shfl_xor_sync(0xffffffffu, d, o);
        dist[c] = d;
    }
    int k = 0;
    float dmin = dist[0];
#pragma unroll
    for (int c = 1; c < 9; c++)
        if (dist[c] < dmin) { dmin = dist[c]; k = c; }   // first-min tie break
    const int k1 = k / 3, k2 = k % 3;

    if (lane == 0) g_K[b] = k;

    const float q0 = emb[k * LAT + lane];
    const float q1 = emb[k * LAT + lane + 32];

    float dc0 = z0 - q0, dc1 = z1 - q1;
    float commit = dc0 * dc0 + dc1 * dc1;
    float som    = commit;

    if (k1 < 2) {
        int idx = (k1 + 1) * 3 + k2;
        float e0 = emb[idx * LAT + lane], e1 = emb[idx * LAT + lane + 32];
        float a = z0 - e0, bb = z1 - e1; som += a * a + bb * bb;
    } else som += z0 * z0 + z1 * z1;
    if (k1 > 0) {
        int idx = (k1 - 1) * 3 + k2;
        float e0 = emb[idx * LAT + lane], e1 = emb[idx * LAT + lane + 32];
        float a = z0 - e0, bb = z1 - e1; som += a * a + bb * bb;
    } else som += z0 * z0 + z1 * z1;
    if (k2 < 2) {
        int idx = k1 * 3 + (k2 + 1);
        float e0 = emb[idx * LAT + lane], e1 = emb[idx * LAT + lane + 32];
        float a = z0 - e0, bb = z1 - e1; som += a * a + bb * bb;
    } else som += z0 * z0 + z1 * z1;
    if (k2 > 0) {
        int idx = k1 * 3 + (k2 - 1);
        float e0 = emb[idx * LAT + lane], e1 = emb[idx * LAT + lane + 32];
        float a = z0 - e0, bb = z1 - e1; som += a * a + bb * bb;
    } else som += z0 * z0 + z1 * z1;

    __shared__ double r0[256], r1[256];
    r0[tid] = (double)commit;
    r1[tid] = (double)som;
    __syncthreads();
    for (int o = 128; o > 0; o >>= 1) {
        if (tid < o) { r0[tid] += r0[tid + o]; r1[tid] += r1[tid + o]; }
        __syncthreads();
    }
    if (tid == 0) {
        g_commit[blockIdx.x] = r0[0];
        g_som[blockIdx.x]    = r1[0];
    }
}

// ---------------- elementwise: out = Table[k[b]] + x_e, MSE partial sums ------
// NOTE: `out` points at d_out+1 (loss occupies d_out[0]) -> only 4-byte aligned.
// Vector loads from x / g_Xe / g_Tq are fine (16B-aligned); stores to `out`
// MUST be scalar.
__global__ __launch_bounds__(256) void final_elem(
    const float* __restrict__ x, float* __restrict__ out)
{
    const int tid = threadIdx.x;
    const size_t base = (size_t)blockIdx.x * 8192;
    float se = 0.f, sq = 0.f;
#pragma unroll
    for (int it = 0; it < 8; it++) {
        size_t i = base + (size_t)(it * 256 + tid) * 4;
        int b = (int)(i >> 11);
        int j = (int)(i & 2047);
        float4 xv = *(const float4*)(x + i);
        float4 xe = *(const float4*)(g_Xe + i);
        float4 xq = *(const float4*)(g_Tq + (size_t)g_K[b] * DIN + j);
        out[i + 0] = xq.x + xe.x;
        out[i + 1] = xq.y + xe.y;
        out[i + 2] = xq.z + xe.z;
        out[i + 3] = xq.w + xe.w;
        float de, dq;
        de = xv.x - xe.x; se = fmaf(de, de, se); dq = xv.x - xq.x; sq = fmaf(dq, dq, sq);
        de = xv.y - xe.y; se = fmaf(de, de, se); dq = xv.y - xq.y; sq = fmaf(dq, dq, sq);
        de = xv.z - xe.z; se = fmaf(de, de, se); dq = xv.z - xq.z; sq = fmaf(dq, dq, sq);
        de = xv.w - xe.w; se = fmaf(de, de, se); dq = xv.w - xq.w; sq = fmaf(dq, dq, sq);
    }
    __shared__ double r0[256], r1[256];
    r0[tid] = (double)se;
    r1[tid] = (double)sq;
    __syncthreads();
    for (int o = 128; o > 0; o >>= 1) {
        if (tid < o) { r0[tid] += r0[tid + o]; r1[tid] += r1[tid + o]; }
        __syncthreads();
    }
    if (tid == 0) {
        g_mse_e[blockIdx.x] = r0[0];
        g_mse_q[blockIdx.x] = r1[0];
    }
}

// ---------------- final loss scalar ----------------
__global__ __launch_bounds__(256) void loss_kernel(float* __restrict__ out)
{
    const int tid = threadIdx.x;
    double c = 0, s = 0, e = 0, q = 0;
    for (int i = tid; i < SOM_BLOCKS; i += 256) { c += g_commit[i]; s += g_som[i]; }
    for (int i = tid; i < EBLK; i += 256)       { e += g_mse_e[i];  q += g_mse_q[i]; }
    __shared__ double r0[256], r1[256], r2[256], r3[256];
    r0[tid] = c; r1[tid] = s; r2[tid] = e; r3[tid] = q;
    __syncthreads();
    for (int o = 128; o > 0; o >>= 1) {
        if (tid < o) {
            r0[tid] += r0[tid + o]; r1[tid] += r1[tid + o];
            r2[tid] += r2[tid + o]; r3[tid] += r3[tid + o];
        }
        __syncthreads();
    }
    if (tid == 0) {
        double mse    = (r2[0] + r3[0]) / (double)NTOT;
        double commit = r0[0] / (double)(B_SZ * LAT);
        double som    = r1[0] / (double)(B_SZ * 5 * LAT);
        out[0] = (float)(mse + commit + som);
    }
}

// ---------------- launch ----------------
extern "C" void kernel_launch(void* const* d_in, const int* in_sizes, int n_in,
                              void* d_out, int out_size)
{
    static float *pH1 = nullptr, *pH2, *pZ, *pXe, *pT1, *pT2, *pTq;
    if (!pH1) {
        cudaGetSymbolAddress((void**)&pH1, g_H1);
        cudaGetSymbolAddress((void**)&pH2, g_H2);
        cudaGetSymbolAddress((void**)&pZ,  g_Z);
        cudaGetSymbolAddress((void**)&pXe, g_Xe);
        cudaGetSymbolAddress((void**)&pT1, g_T1);
        cudaGetSymbolAddress((void**)&pT2, g_T2);
        cudaGetSymbolAddress((void**)&pTq, g_Tq);
    }

    const float* x      = (const float*)d_in[0];
    const float* enc_w1 = (const float*)d_in[2];
    const float* enc_b1 = (const float*)d_in[3];
    const float* enc_w2 = (const float*)d_in[4];
    const float* enc_b2 = (const float*)d_in[5];
    const float* enc_w3 = (const float*)d_in[6];
    const float* enc_b3 = (const float*)d_in[7];
    const float* dq_w1  = (const float*)d_in[8];
    const float* dq_b1  = (const float*)d_in[9];
    const float* dq_w2  = (const float*)d_in[10];
    const float* dq_b2  = (const float*)d_in[11];
    const float* dq_w3  = (const float*)d_in[12];
    const float* dq_b3  = (const float*)d_in[13];
    const float* de_w1  = (const float*)d_in[14];
    const float* de_b1  = (const float*)d_in[15];
    const float* de_w2  = (const float*)d_in[16];
    const float* de_b2  = (const float*)d_in[17];
    const float* de_w3  = (const float*)d_in[18];
    const float* de_b3  = (const float*)d_in[19];
    const float* emb    = (const float*)d_in[20];

    float* out = (float*)d_out;          // out[0] = loss, out[1..] = x_q + x_e

    const dim3 thr(256);
    const dim3 gLAT(LAT / 64, B_SZ / 128);          // fp32 scalar kernel, N=64
    const dim3 tHID(HID / 128, B_SZ / 128);         // tf32 kernel, N=512
    const dim3 tDIN(DIN / 128, B_SZ / 128);         // tf32 kernel, N=2048

    // ---- encoder: L1/L2 in 3xTF32 (error-compensated, argmin-safe), L3 fp32 --
    gemm_tf32<0, 1><<<tHID, thr>>>(x,   enc_w1, enc_b1, pH1, B_SZ, DIN, HID);
    gemm_tf32<0, 1><<<tHID, thr>>>(pH1, enc_w2, enc_b2, pH2, B_SZ, HID, HID);
    gemm_bias_act<1><<<gLAT, thr>>>(pH2, enc_w3, enc_b3, pZ,  B_SZ, HID, LAT);

    // ---- SOM quantization + commit/som loss partials (writes g_K) ----
    som_kernel<<<SOM_BLOCKS, thr>>>(pZ, emb);

    // ---- dq decoder collapsed to a 9-row table (exact fp32) ----
    dq_small<0><<<dim3(HID / 256, 9), thr>>>(emb, dq_w1, dq_b1, pT1, LAT, HID);
    dq_small<0><<<dim3(HID / 256, 9), thr>>>(pT1, dq_w2, dq_b2, pT2, HID, HID);
    dq_small<2><<<dim3(DIN / 256, 9), thr>>>(pT2, dq_w3, dq_b3, pTq, HID, DIN);

    // ---- e-decoder in single-pass TF32 ----
    gemm_tf32<0, 0><<<tHID, thr>>>(pZ,  de_w1, de_b1, pH1, B_SZ, LAT, HID);
    gemm_tf32<0, 0><<<tHID, thr>>>(pH1, de_w2, de_b2, pH2, B_SZ, HID, HID);
    gemm_tf32<2, 0><<<tDIN, thr>>>(pH2, de_w3, de_b3, pXe, B_SZ, HID, DIN);

    // ---- output tensor + loss ----
    final_elem<<<EBLK, thr>>>(x, out + 1);
    loss_kernel<<<1, thr>>>(out);
}

// round 10
// speedup vs baseline: 2.1274x; 1.2266x over previous
#include <cuda_runtime.h>
#include <math.h>
#include <stdint.h>

// ---------------- problem constants ----------------
#define B_SZ   16384
#define DIN    2048          // S*C
#define HID    512
#define LAT    64
#define NTOT   (B_SZ * DIN)  // 33,554,432

#define SOM_BLOCKS (B_SZ / 8)  // 2048
#define EBLK 4096              // blocks for elementwise/mse kernel

// tf32 pipelined GEMM smem layout
#define PADK 20                // A tile row pitch ([m][k] layout, 16 k + 4 pad)
#define PADN 136               // B tile row pitch ([k][n] layout, 128 n + 8 pad)
#define A_STG (128 * PADK)     // floats per A stage
#define B_STG (16 * PADN)      // floats per B stage
#define SMEM_F_NOSPLIT (2 * A_STG + 2 * B_STG)                  // 9472 floats
#define SMEM_F_SPLIT   (2 * (2 * A_STG + 2 * B_STG))            // 18944 floats

// ---------------- scratch (device globals; allocation-free rule) --------------
__device__ float g_H1[B_SZ * HID];
__device__ float g_H2[B_SZ * HID];
__device__ float g_Z [B_SZ * LAT];
__device__ float g_Xe[(size_t)B_SZ * DIN];
__device__ int   g_K [B_SZ];

__device__ float g_T1[9 * HID];
__device__ float g_T2[9 * HID];
__device__ float g_Tq[9 * DIN];

__device__ double g_commit[SOM_BLOCKS];
__device__ double g_som   [SOM_BLOCKS];
__device__ double g_mse_e [EBLK];
__device__ double g_mse_q [EBLK];

// ---------------- fp32 GEMM + bias + activation (small encoder layer 3) -------
// ACT: 0 = relu, 1 = tanh, 2 = none
template<int ACT>
__global__ __launch_bounds__(256) void gemm_bias_act(
    const float* __restrict__ A, const float* __restrict__ W,
    const float* __restrict__ bias, float* __restrict__ C,
    int M, int K, int N)
{
    __shared__ float As[16][132];
    __shared__ float Bs[16][64];

    const int tid = threadIdx.x;
    const int tx  = tid & 15;
    const int ty  = tid >> 4;
    const int m0  = blockIdx.y * 128;
    const int n0  = blockIdx.x * 64;

    float acc[8][4];
#pragma unroll
    for (int i = 0; i < 8; i++)
#pragma unroll
        for (int j = 0; j < 4; j++) acc[i][j] = 0.f;

    for (int k0 = 0; k0 < K; k0 += 16) {
#pragma unroll
        for (int i = 0; i < 2; i++) {
            int f  = tid + i * 256;
            int r  = f >> 2;
            int c4 = f & 3;
            float4 v = *(const float4*)(A + (size_t)(m0 + r) * K + k0 + c4 * 4);
            As[c4 * 4 + 0][r] = v.x;
            As[c4 * 4 + 1][r] = v.y;
            As[c4 * 4 + 2][r] = v.z;
            As[c4 * 4 + 3][r] = v.w;
        }
        {
            int r  = tid >> 4;
            int c4 = tid & 15;
            *(float4*)&Bs[r][c4 * 4] =
                *(const float4*)(W + (size_t)(k0 + r) * N + n0 + c4 * 4);
        }
        __syncthreads();

#pragma unroll
        for (int k = 0; k < 16; k++) {
            float a[8], b[4];
            *(float4*)&a[0] = *(const float4*)&As[k][ty * 8];
            *(float4*)&a[4] = *(const float4*)&As[k][ty * 8 + 4];
            *(float4*)&b[0] = *(const float4*)&Bs[k][tx * 4];
#pragma unroll
            for (int i = 0; i < 8; i++)
#pragma unroll
                for (int j = 0; j < 4; j++)
                    acc[i][j] = fmaf(a[i], b[j], acc[i][j]);
        }
        __syncthreads();
    }

    float bv[4];
#pragma unroll
    for (int j = 0; j < 4; j++) bv[j] = bias[n0 + tx * 4 + j];

#pragma unroll
    for (int i = 0; i < 8; i++) {
        int m = m0 + ty * 8 + i;
        float4 o;
        float* po = (float*)&o;
#pragma unroll
        for (int j = 0; j < 4; j++) {
            float v = acc[i][j] + bv[j];
            if (ACT == 0)      v = fmaxf(v, 0.f);
            else if (ACT == 1) v = tanhf(v);
            po[j] = v;
        }
        *(float4*)(C + (size_t)m * N + n0 + tx * 4) = o;
    }
}

// ---------------- TF32 tensor-core GEMM, double-buffered pipeline -------------
__device__ __forceinline__ float to_tf32(float x) {
    uint32_t y;
    asm("cvt.rna.tf32.f32 %0, %1;" : "=r"(y) : "f"(x));
    return __uint_as_float(y);
}

__device__ __forceinline__ void mma_tf32(float* c, const uint32_t* a, const uint32_t* b) {
    asm volatile(
        "mma.sync.aligned.m16n8k8.row.col.f32.tf32.tf32.f32 "
        "{%0,%1,%2,%3}, {%4,%5,%6,%7}, {%8,%9}, {%0,%1,%2,%3};\n"
        : "+f"(c[0]), "+f"(c[1]), "+f"(c[2]), "+f"(c[3])
        : "r"(a[0]), "r"(a[1]), "r"(a[2]), "r"(a[3]), "r"(b[0]), "r"(b[1]));
}

// BM=128, BN=128, BK=16, 256 threads (8 warps, 4x2), warp tile 32x64.
// A in smem [m][k] pad PADK (conflict-free LDS, vector STS);
// B in smem [k][n] pad PADN (conflict-free LDS, vector STS).
// Double-buffered, one __syncthreads per K-tile.
// ACT: 0 = relu, 1 = tanh, 2 = none.  SPLIT=1: 3xTF32 error-compensated.
template<int ACT, int SPLIT>
__global__ __launch_bounds__(256) void gemm_tf32(
    const float* __restrict__ A, const float* __restrict__ W,
    const float* __restrict__ bias, float* __restrict__ C,
    int M, int K, int N)
{
    extern __shared__ float sm[];
    float* Ah = sm;                      // 2 stages [128][PADK]
    float* Bh = sm + 2 * A_STG;          // 2 stages [16][PADN]
    float* Al = Bh + 2 * B_STG;          // (SPLIT) 2 stages
    float* Bl = Al + 2 * A_STG;          // (SPLIT) 2 stages

    const int tid  = threadIdx.x;
    const int warp = tid >> 5, lane = tid & 31;
    const int gid  = lane >> 2, t4 = lane & 3;
    const int wm   = warp >> 1, wn = warp & 1;
    const int m0   = blockIdx.y * 128, n0 = blockIdx.x * 128;

    float4 rA[2], rB[2];   // staging registers for the next tile

    auto ldg = [&](int t) {
        const int k0 = t * 16;
#pragma unroll
        for (int i = 0; i < 2; i++) {
            int f = tid + i * 256;
            int r = f >> 2, c4 = f & 3;
            rA[i] = *(const float4*)(A + (size_t)(m0 + r) * K + k0 + c4 * 4);
        }
#pragma unroll
        for (int i = 0; i < 2; i++) {
            int f = tid + i * 256;
            int r = f >> 5, c4 = f & 31;
            rB[i] = *(const float4*)(W + (size_t)(k0 + r) * N + n0 + c4 * 4);
        }
    };

    auto sts = [&](int s) {
        float* ah = Ah + s * A_STG;
        float* bh = Bh + s * B_STG;
#pragma unroll
        for (int i = 0; i < 2; i++) {
            int f = tid + i * 256;
            int r = f >> 2, c4 = f & 3;
            float h0 = to_tf32(rA[i].x), h1 = to_tf32(rA[i].y);
            float h2 = to_tf32(rA[i].z), h3 = to_tf32(rA[i].w);
            *(float4*)(ah + r * PADK + c4 * 4) = make_float4(h0, h1, h2, h3);
            if (SPLIT) {
                float* al = Al + s * A_STG;
                *(float4*)(al + r * PADK + c4 * 4) = make_float4(
                    to_tf32(rA[i].x - h0), to_tf32(rA[i].y - h1),
                    to_tf32(rA[i].z - h2), to_tf32(rA[i].w - h3));
            }
        }
#pragma unroll
        for (int i = 0; i < 2; i++) {
            int f = tid + i * 256;
            int r = f >> 5, c4 = f & 31;
            float h0 = to_tf32(rB[i].x), h1 = to_tf32(rB[i].y);
            float h2 = to_tf32(rB[i].z), h3 = to_tf32(rB[i].w);
            *(float4*)(bh + r * PADN + c4 * 4) = make_float4(h0, h1, h2, h3);
            if (SPLIT) {
                float* bl = Bl + s * B_STG;
                *(float4*)(bl + r * PADN + c4 * 4) = make_float4(
                    to_tf32(rB[i].x - h0), to_tf32(rB[i].y - h1),
                    to_tf32(rB[i].z - h2), to_tf32(rB[i].w - h3));
            }
        }
    };

    float acc[2][8][4];
#pragma unroll
    for (int mt = 0; mt < 2; mt++)
#pragma unroll
        for (int nt = 0; nt < 8; nt++)
#pragma unroll
            for (int j = 0; j < 4; j++) acc[mt][nt][j] = 0.f;

    const int T = K / 16;
    ldg(0);
    sts(0);
    __syncthreads();
    if (T > 1) ldg(1);

    for (int t = 0; t < T; t++) {
        const int cur = t & 1, nxt = (t + 1) & 1;
        if (t + 1 < T) sts(nxt);      // publish tile t+1 into other buffer
        if (t + 2 < T) ldg(t + 2);    // issue loads for tile t+2 (hidden by mma)

        const float* ah = Ah + cur * A_STG;
        const float* bh = Bh + cur * B_STG;
        const float* al = Al + cur * A_STG;
        const float* bl = Bl + cur * B_STG;

#pragma unroll
        for (int kk = 0; kk < 2; kk++) {
            const int kb = kk * 8;
            uint32_t af[2][4], afl[2][4];
#pragma unroll
            for (int mt = 0; mt < 2; mt++) {
                int rb = wm * 32 + mt * 16;
                af[mt][0] = __float_as_uint(ah[(rb + gid    ) * PADK + kb + t4    ]);
                af[mt][1] = __float_as_uint(ah[(rb + gid + 8) * PADK + kb + t4    ]);
                af[mt][2] = __float_as_uint(ah[(rb + gid    ) * PADK + kb + t4 + 4]);
                af[mt][3] = __float_as_uint(ah[(rb + gid + 8) * PADK + kb + t4 + 4]);
                if (SPLIT) {
                    afl[mt][0] = __float_as_uint(al[(rb + gid    ) * PADK + kb + t4    ]);
                    afl[mt][1] = __float_as_uint(al[(rb + gid + 8) * PADK + kb + t4    ]);
                    afl[mt][2] = __float_as_uint(al[(rb + gid    ) * PADK + kb + t4 + 4]);
                    afl[mt][3] = __float_as_uint(al[(rb + gid + 8) * PADK + kb + t4 + 4]);
                }
            }
#pragma unroll
            for (int nt = 0; nt < 8; nt++) {
                int cb = wn * 64 + nt * 8 + gid;
                uint32_t bf[2];
                bf[0] = __float_as_uint(bh[(kb + t4    ) * PADN + cb]);
                bf[1] = __float_as_uint(bh[(kb + t4 + 4) * PADN + cb]);
#pragma unroll
                for (int mt = 0; mt < 2; mt++)
                    mma_tf32(acc[mt][nt], af[mt], bf);
                if (SPLIT) {
                    uint32_t blf[2];
                    blf[0] = __float_as_uint(bl[(kb + t4    ) * PADN + cb]);
                    blf[1] = __float_as_uint(bl[(kb + t4 + 4) * PADN + cb]);
#pragma unroll
                    for (int mt = 0; mt < 2; mt++) {
                        mma_tf32(acc[mt][nt], af[mt], blf);   // hi_a * lo_b
                        mma_tf32(acc[mt][nt], afl[mt], bf);   // lo_a * hi_b
                    }
                }
            }
        }
        __syncthreads();
    }

    // epilogue: bias + activation, float2 stores
#pragma unroll
    for (int mt = 0; mt < 2; mt++) {
        int r0 = m0 + wm * 32 + mt * 16 + gid;
#pragma unroll
        for (int nt = 0; nt < 8; nt++) {
            int c = n0 + wn * 64 + nt * 8 + 2 * t4;
            float b0 = bias[c], b1 = bias[c + 1];
            float v00 = acc[mt][nt][0] + b0, v01 = acc[mt][nt][1] + b1;
            float v10 = acc[mt][nt][2] + b0, v11 = acc[mt][nt][3] + b1;
            if (ACT == 0) {
                v00 = fmaxf(v00, 0.f); v01 = fmaxf(v01, 0.f);
                v10 = fmaxf(v10, 0.f); v11 = fmaxf(v11, 0.f);
            } else if (ACT == 1) {
                v00 = tanhf(v00); v01 = tanhf(v01);
                v10 = tanhf(v10); v11 = tanhf(v11);
            }
            *(float2*)(C + (size_t)r0 * N + c)       = make_float2(v00, v01);
            *(float2*)(C + (size_t)(r0 + 8) * N + c) = make_float2(v10, v11);
        }
    }
}

// ---------------- tiny GEMM for the 9-row dq-decoder table --------------------
template<int ACT>
__global__ __launch_bounds__(256) void dq_small(
    const float* __restrict__ A, const float* __restrict__ W,
    const float* __restrict__ bias, float* __restrict__ C,
    int K, int N)
{
    const int row = blockIdx.y;
    const int n   = blockIdx.x * 256 + threadIdx.x;
    const float* a = A + (size_t)row * K;
    float acc = 0.f;
    for (int k = 0; k < K; k++)
        acc = fmaf(a[k], W[(size_t)k * N + n], acc);
    acc += bias[n];
    if (ACT == 0) acc = fmaxf(acc, 0.f);
    C[(size_t)row * N + n] = acc;
}

// ---------------- SOM: argmin over 9 codes, commit & som partial losses -------
__global__ __launch_bounds__(256) void som_kernel(
    const float* __restrict__ Z, const float* __restrict__ emb)
{
    const int tid  = threadIdx.x;
    const int warp = tid >> 5;
    const int lane = tid & 31;
    const int b    = blockIdx.x * 8 + warp;

    const float* z = Z + (size_t)b * LAT;
    const float z0 = z[lane];
    const float z1 = z[lane + 32];

    float dist[9];
#pragma unroll
    for (int c = 0; c < 9; c++) {
        float e0 = emb[c * LAT + lane];
        float e1 = emb[c * LAT + lane + 32];
        float d0 = z0 - e0, d1 = z1 - e1;
        float d = d0 * d0 + d1 * d1;
#pragma unroll
        for (int o = 16; o > 0; o >>= 1)
            d += __shfl_xor_sync(0xffffffffu, d, o);
        dist[c] = d;
    }
    int k = 0;
    float dmin = dist[0];
#pragma unroll
    for (int c = 1; c < 9; c++)
        if (dist[c] < dmin) { dmin = dist[c]; k = c; }   // first-min tie break
    const int k1 = k / 3, k2 = k % 3;

    if (lane == 0) g_K[b] = k;

    const float q0 = emb[k * LAT + lane];
    const float q1 = emb[k * LAT + lane + 32];

    float dc0 = z0 - q0, dc1 = z1 - q1;
    float commit = dc0 * dc0 + dc1 * dc1;
    float som    = commit;

    if (k1 < 2) {
        int idx = (k1 + 1) * 3 + k2;
        float e0 = emb[idx * LAT + lane], e1 = emb[idx * LAT + lane + 32];
        float a = z0 - e0, bb = z1 - e1; som += a * a + bb * bb;
    } else som += z0 * z0 + z1 * z1;
    if (k1 > 0) {
        int idx = (k1 - 1) * 3 + k2;
        float e0 = emb[idx * LAT + lane], e1 = emb[idx * LAT + lane + 32];
        float a = z0 - e0, bb = z1 - e1; som += a * a + bb * bb;
    } else som += z0 * z0 + z1 * z1;
    if (k2 < 2) {
        int idx = k1 * 3 + (k2 + 1);
        float e0 = emb[idx * LAT + lane], e1 = emb[idx * LAT + lane + 32];
        float a = z0 - e0, bb = z1 - e1; som += a * a + bb * bb;
    } else som += z0 * z0 + z1 * z1;
    if (k2 > 0) {
        int idx = k1 * 3 + (k2 - 1);
        float e0 = emb[idx * LAT + lane], e1 = emb[idx * LAT + lane + 32];
        float a = z0 - e0, bb = z1 - e1; som += a * a + bb * bb;
    } else som += z0 * z0 + z1 * z1;

    __shared__ double r0[256], r1[256];
    r0[tid] = (double)commit;
    r1[tid] = (double)som;
    __syncthreads();
    for (int o = 128; o > 0; o >>= 1) {
        if (tid < o) { r0[tid] += r0[tid + o]; r1[tid] += r1[tid + o]; }
        __syncthreads();
    }
    if (tid == 0) {
        g_commit[blockIdx.x] = r0[0];
        g_som[blockIdx.x]    = r1[0];
    }
}

// ---------------- elementwise: out = Table[k[b]] + x_e, MSE partial sums ------
// `out` = d_out+1 -> only 4B-aligned: stores MUST be scalar.
__global__ __launch_bounds__(256) void final_elem(
    const float* __restrict__ x, float* __restrict__ out)
{
    const int tid = threadIdx.x;
    const size_t base = (size_t)blockIdx.x * 8192;
    float se = 0.f, sq = 0.f;
#pragma unroll
    for (int it = 0; it < 8; it++) {
        size_t i = base + (size_t)(it * 256 + tid) * 4;
        int b = (int)(i >> 11);
        int j = (int)(i & 2047);
        float4 xv = *(const float4*)(x + i);
        float4 xe = *(const float4*)(g_Xe + i);
        float4 xq = *(const float4*)(g_Tq + (size_t)g_K[b] * DIN + j);
        out[i + 0] = xq.x + xe.x;
        out[i + 1] = xq.y + xe.y;
        out[i + 2] = xq.z + xe.z;
        out[i + 3] = xq.w + xe.w;
        float de, dq;
        de = xv.x - xe.x; se = fmaf(de, de, se); dq = xv.x - xq.x; sq = fmaf(dq, dq, sq);
        de = xv.y - xe.y; se = fmaf(de, de, se); dq = xv.y - xq.y; sq = fmaf(dq, dq, sq);
        de = xv.z - xe.z; se = fmaf(de, de, se); dq = xv.z - xq.z; sq = fmaf(dq, dq, sq);
        de = xv.w - xe.w; se = fmaf(de, de, se); dq = xv.w - xq.w; sq = fmaf(dq, dq, sq);
    }
    __shared__ double r0[256], r1[256];
    r0[tid] = (double)se;
    r1[tid] = (double)sq;
    __syncthreads();
    for (int o = 128; o > 0; o >>= 1) {
        if (tid < o) { r0[tid] += r0[tid + o]; r1[tid] += r1[tid + o]; }
        __syncthreads();
    }
    if (tid == 0) {
        g_mse_e[blockIdx.x] = r0[0];
        g_mse_q[blockIdx.x] = r1[0];
    }
}

// ---------------- final loss scalar ----------------
__global__ __launch_bounds__(256) void loss_kernel(float* __restrict__ out)
{
    const int tid = threadIdx.x;
    double c = 0, s = 0, e = 0, q = 0;
    for (int i = tid; i < SOM_BLOCKS; i += 256) { c += g_commit[i]; s += g_som[i]; }
    for (int i = tid; i < EBLK; i += 256)       { e += g_mse_e[i];  q += g_mse_q[i]; }
    __shared__ double r0[256], r1[256], r2[256], r3[256];
    r0[tid] = c; r1[tid] = s; r2[tid] = e; r3[tid] = q;
    __syncthreads();
    for (int o = 128; o > 0; o >>= 1) {
        if (tid < o) {
            r0[tid] += r0[tid + o]; r1[tid] += r1[tid + o];
            r2[tid] += r2[tid + o]; r3[tid] += r3[tid + o];
        }
        __syncthreads();
    }
    if (tid == 0) {
        double mse    = (r2[0] + r3[0]) / (double)NTOT;
        double commit = r0[0] / (double)(B_SZ * LAT);
        double som    = r1[0] / (double)(B_SZ * 5 * LAT);
        out[0] = (float)(mse + commit + som);
    }
}

// ---------------- launch ----------------
extern "C" void kernel_launch(void* const* d_in, const int* in_sizes, int n_in,
                              void* d_out, int out_size)
{
    static float *pH1 = nullptr, *pH2, *pZ, *pXe, *pT1, *pT2, *pTq;
    if (!pH1) {
        cudaGetSymbolAddress((void**)&pH1, g_H1);
        cudaGetSymbolAddress((void**)&pH2, g_H2);
        cudaGetSymbolAddress((void**)&pZ,  g_Z);
        cudaGetSymbolAddress((void**)&pXe, g_Xe);
        cudaGetSymbolAddress((void**)&pT1, g_T1);
        cudaGetSymbolAddress((void**)&pT2, g_T2);
        cudaGetSymbolAddress((void**)&pTq, g_Tq);
        // SPLIT variant needs >48KB dynamic smem; set opt-in once (first call
        // happens before graph capture).
        cudaFuncSetAttribute(gemm_tf32<0, 1>,
                             cudaFuncAttributeMaxDynamicSharedMemorySize,
                             SMEM_F_SPLIT * 4);
    }

    const float* x      = (const float*)d_in[0];
    const float* enc_w1 = (const float*)d_in[2];
    const float* enc_b1 = (const float*)d_in[3];
    const float* enc_w2 = (const float*)d_in[4];
    const float* enc_b2 = (const float*)d_in[5];
    const float* enc_w3 = (const float*)d_in[6];
    const float* enc_b3 = (const float*)d_in[7];
    const float* dq_w1  = (const float*)d_in[8];
    const float* dq_b1  = (const float*)d_in[9];
    const float* dq_w2  = (const float*)d_in[10];
    const float* dq_b2  = (const float*)d_in[11];
    const float* dq_w3  = (const float*)d_in[12];
    const float* dq_b3  = (const float*)d_in[13];
    const float* de_w1  = (const float*)d_in[14];
    const float* de_b1  = (const float*)d_in[15];
    const float* de_w2  = (const float*)d_in[16];
    const float* de_b2  = (const float*)d_in[17];
    const float* de_w3  = (const float*)d_in[18];
    const float* de_b3  = (const float*)d_in[19];
    const float* emb    = (const float*)d_in[20];

    float* out = (float*)d_out;          // out[0] = loss, out[1..] = x_q + x_e

    const dim3 thr(256);
    const dim3 gLAT(LAT / 64, B_SZ / 128);          // fp32 scalar kernel, N=64
    const dim3 tHID(HID / 128, B_SZ / 128);         // tf32 kernel, N=512
    const dim3 tDIN(DIN / 128, B_SZ / 128);         // tf32 kernel, N=2048

    const size_t smem_ns = SMEM_F_NOSPLIT * 4;      // 37,888 B
    const size_t smem_sp = SMEM_F_SPLIT * 4;        // 75,776 B

    // ---- encoder: L1/L2 in 3xTF32 (error-compensated, argmin-safe), L3 fp32 --
    gemm_tf32<0, 1><<<tHID, thr, smem_sp>>>(x,   enc_w1, enc_b1, pH1, B_SZ, DIN, HID);
    gemm_tf32<0, 1><<<tHID, thr, smem_sp>>>(pH1, enc_w2, enc_b2, pH2, B_SZ, HID, HID);
    gemm_bias_act<1><<<gLAT, thr>>>(pH2, enc_w3, enc_b3, pZ,  B_SZ, HID, LAT);

    // ---- SOM quantization + commit/som loss partials (writes g_K) ----
    som_kernel<<<SOM_BLOCKS, thr>>>(pZ, emb);

    // ---- dq decoder collapsed to a 9-row table (exact fp32) ----
    dq_small<0><<<dim3(HID / 256, 9), thr>>>(emb, dq_w1, dq_b1, pT1, LAT, HID);
    dq_small<0><<<dim3(HID / 256, 9), thr>>>(pT1, dq_w2, dq_b2, pT2, HID, HID);
    dq_small<2><<<dim3(DIN / 256, 9), thr>>>(pT2, dq_w3, dq_b3, pTq, HID, DIN);

    // ---- e-decoder in single-pass TF32 ----
    gemm_tf32<0, 0><<<tHID, thr, smem_ns>>>(pZ,  de_w1, de_b1, pH1, B_SZ, LAT, HID);
    gemm_tf32<0, 0><<<tHID, thr, smem_ns>>>(pH1, de_w2, de_b2, pH2, B_SZ, HID, HID);
    gemm_tf32<2, 0><<<tDIN, thr, smem_ns>>>(pH2, de_w3, de_b3, pXe, B_SZ, HID, DIN);

    // ---- output tensor + loss ----
    final_elem<<<EBLK, thr>>>(x, out + 1);
    loss_kernel<<<1, thr>>>(out);
}